// round 4
// baseline (speedup 1.0000x reference)
#include <cuda_runtime.h>
#include <math.h>

#define NN 50000          // nodes
#define NF 128            // feature width (layer-1 in, layer-2 out)
#define NH 256            // hidden width
#define EMAX 800000
#define PMAX 100000

// ---- scratch (device globals; no allocation allowed) ----
__device__ int   g_is64;
__device__ int   g_row [EMAX];
__device__ int   g_col [EMAX];
__device__ int   g_ma  [PMAX];
__device__ int   g_mb  [PMAX];
__device__ float g_deg [NN];
__device__ float g_dinv[NN];
__device__ float g_Y1  [(size_t)NN * NF];   // S @ X
__device__ float g_H1  [(size_t)NN * NH];   // relu(Y1 @ W1 + b1)
__device__ float g_Z   [(size_t)NN * NF];   // H1 @ W2
__device__ float g_H2  [(size_t)NN * NF];   // S @ Z + b2

// ---------------------------------------------------- index dtype detect
// If the buffer really holds int64 node ids, every value is in [0, NN).
// If it holds int32, the int64 view fuses random pairs -> astronomically
// large values. Sample 8 entries; all-valid => int64.
__global__ void k_detect(const void* __restrict__ ei) {
    const long long* p = (const long long*)ei;
    int ok = 1;
    for (int i = 0; i < 8; i++) {
        long long v = p[i];
        if (v < 0 || v >= NN) ok = 0;
    }
    g_is64 = ok;
}

__global__ void k_convert_edges(const void* __restrict__ ei, int E) {
    int e = blockIdx.x * blockDim.x + threadIdx.x;
    if (e >= E) return;
    int r, c;
    if (g_is64) {
        const long long* p = (const long long*)ei;
        r = (int)p[e];
        c = (int)p[(size_t)E + e];
    } else {
        const int* p = (const int*)ei;
        r = p[e];
        c = p[E + e];
    }
    g_row[e] = r;
    g_col[e] = c;
}

__global__ void k_convert_mask(const void* __restrict__ mask, int P) {
    int i = blockIdx.x * blockDim.x + threadIdx.x;
    if (i >= P) return;
    int a, b;
    if (g_is64) {
        const long long* p = (const long long*)mask;
        a = (int)p[(size_t)i * 2 + 0];
        b = (int)p[(size_t)i * 2 + 1];
    } else {
        const int* p = (const int*)mask;
        a = p[i * 2 + 0];
        b = p[i * 2 + 1];
    }
    g_ma[i] = a;
    g_mb[i] = b;
}

// ---------------------------------------------------------------- degree
__global__ void k_init_deg() {
    int i = blockIdx.x * blockDim.x + threadIdx.x;
    if (i < NN) g_deg[i] = 1.0f;              // self loop
}

__global__ void k_count_deg(int E) {
    int e = blockIdx.x * blockDim.x + threadIdx.x;
    if (e < E) atomicAdd(&g_deg[g_col[e]], 1.0f);
}

__global__ void k_dinv() {
    int i = blockIdx.x * blockDim.x + threadIdx.x;
    if (i < NN) g_dinv[i] = rsqrtf(g_deg[i]); // deg >= 1 always
}

// ------------------------------------------------- self-loop init (+bias)
// dst[i][f] = dinv[i]^2 * src[i][f] (+ bias[f]); operates on float4 lanes
__global__ void k_selfloop_init(const float* __restrict__ src,
                                float* __restrict__ dst,
                                const float* __restrict__ bias) {
    int idx = blockIdx.x * blockDim.x + threadIdx.x;      // over NN*32 float4
    if (idx >= NN * (NF / 4)) return;
    int node = idx >> 5;
    int f4   = idx & 31;
    float w = g_dinv[node] * g_dinv[node];
    float4 v = ((const float4*)src)[idx];
    float4 o;
    o.x = w * v.x; o.y = w * v.y; o.z = w * v.z; o.w = w * v.w;
    if (bias) {
        float4 b = ((const float4*)bias)[f4];
        o.x += b.x; o.y += b.y; o.z += b.z; o.w += b.w;
    }
    ((float4*)dst)[idx] = o;
}

// ---------------------------------------------------------------- scatter
// warp per edge: dst[col] += dinv[row]*dinv[col] * src[row]   (128 floats)
__global__ void k_scatter(const float* __restrict__ src,
                          float* __restrict__ dst, int E) {
    int warp = (blockIdx.x * blockDim.x + threadIdx.x) >> 5;
    if (warp >= E) return;
    int lane = threadIdx.x & 31;
    int r = g_row[warp];
    int c = g_col[warp];
    float w = g_dinv[r] * g_dinv[c];
    float4 v = ((const float4*)(src + (size_t)r * NF))[lane];
    float* d = dst + (size_t)c * NF + lane * 4;
    atomicAdd(d + 0, w * v.x);
    atomicAdd(d + 1, w * v.y);
    atomicAdd(d + 2, w * v.z);
    atomicAdd(d + 3, w * v.w);
}

// ------------------------------------------------------------------ SGEMM
// C[M,N] = A[M,K] @ B[K,N]  (+bias per col)  (optional relu)
// BM=BN=128, BK=16, 256 threads, 8x8 micro-tile (split 4+4 rows/cols)
__global__ __launch_bounds__(256)
void k_sgemm(const float* __restrict__ A, const float* __restrict__ B,
             const float* __restrict__ bias, float* __restrict__ C,
             int M, int N, int K, int relu) {
    const int BM = 128, BN = 128, BK = 16;
    __shared__ float As[BK * BM];   // transposed: As[k][m]
    __shared__ float Bs[BK * BN];   // Bs[k][n]

    int tid = threadIdx.x;
    int tx = tid & 15;              // col group 0..15
    int ty = tid >> 4;              // row group 0..15
    int rowBlock = blockIdx.x * BM;
    int colBlock = blockIdx.y * BN;

    float acc[8][8];
#pragma unroll
    for (int i = 0; i < 8; i++)
#pragma unroll
        for (int j = 0; j < 8; j++) acc[i][j] = 0.0f;

    for (int k0 = 0; k0 < K; k0 += BK) {
#pragma unroll
        for (int l = 0; l < 2; l++) {
            int fi = tid + l * 256;                 // 0..511 float4 slots
            // --- A tile: row = fi/4, k-offset = (fi%4)*4 ---
            int ar = fi >> 2;
            int ak = (fi & 3) << 2;
            float4 v = make_float4(0.f, 0.f, 0.f, 0.f);
            int grow = rowBlock + ar;
            if (grow < M)
                v = *(const float4*)(A + (size_t)grow * K + k0 + ak);
            As[(ak + 0) * BM + ar] = v.x;
            As[(ak + 1) * BM + ar] = v.y;
            As[(ak + 2) * BM + ar] = v.z;
            As[(ak + 3) * BM + ar] = v.w;
            // --- B tile: k = fi/32, n-offset = (fi%32)*4 ---
            int bk = fi >> 5;
            int bn = (fi & 31) << 2;
            float4 w = *(const float4*)(B + (size_t)(k0 + bk) * N + colBlock + bn);
            *(float4*)&Bs[bk * BN + bn] = w;
        }
        __syncthreads();

#pragma unroll
        for (int kk = 0; kk < BK; kk++) {
            float a0[4], a1[4], b0[4], b1[4];
            *(float4*)a0 = *(const float4*)&As[kk * BM + ty * 4];
            *(float4*)a1 = *(const float4*)&As[kk * BM + 64 + ty * 4];
            *(float4*)b0 = *(const float4*)&Bs[kk * BN + tx * 4];
            *(float4*)b1 = *(const float4*)&Bs[kk * BN + 64 + tx * 4];
#pragma unroll
            for (int i = 0; i < 4; i++) {
#pragma unroll
                for (int j = 0; j < 4; j++) {
                    acc[i][j]         += a0[i] * b0[j];
                    acc[i][j + 4]     += a0[i] * b1[j];
                    acc[i + 4][j]     += a1[i] * b0[j];
                    acc[i + 4][j + 4] += a1[i] * b1[j];
                }
            }
        }
        __syncthreads();
    }

    // epilogue
#pragma unroll
    for (int ih = 0; ih < 2; ih++) {
#pragma unroll
        for (int i = 0; i < 4; i++) {
            int row = rowBlock + ih * 64 + ty * 4 + i;
            if (row >= M) continue;
#pragma unroll
            for (int jh = 0; jh < 2; jh++) {
                int col = colBlock + jh * 64 + tx * 4;
                float* a = &acc[ih * 4 + i][jh * 4];
                float4 o = make_float4(a[0], a[1], a[2], a[3]);
                if (bias) {
                    float4 b = *(const float4*)(bias + col);
                    o.x += b.x; o.y += b.y; o.z += b.z; o.w += b.w;
                }
                if (relu) {
                    o.x = fmaxf(o.x, 0.f); o.y = fmaxf(o.y, 0.f);
                    o.z = fmaxf(o.z, 0.f); o.w = fmaxf(o.w, 0.f);
                }
                *(float4*)(C + (size_t)row * N + col) = o;
            }
        }
    }
}

// --------------------------------------------------------------- pair dot
// warp per pair: out[p] = sigmoid( H2[m0].Wl[0:128] + H2[m1].Wl[128:256] + bl )
__global__ void k_pairs(const float* __restrict__ Wl,
                        const float* __restrict__ bl,
                        float* __restrict__ out, int P) {
    int warp = (blockIdx.x * blockDim.x + threadIdx.x) >> 5;
    if (warp >= P) return;
    int lane = threadIdx.x & 31;
    int a = g_ma[warp];
    int b = g_mb[warp];
    float4 va = ((const float4*)(g_H2 + (size_t)a * NF))[lane];
    float4 wa = ((const float4*)Wl)[lane];
    float4 vb = ((const float4*)(g_H2 + (size_t)b * NF))[lane];
    float4 wb = ((const float4*)(Wl + NF))[lane];
    float acc = va.x * wa.x + va.y * wa.y + va.z * wa.z + va.w * wa.w
              + vb.x * wb.x + vb.y * wb.y + vb.z * wb.z + vb.w * wb.w;
#pragma unroll
    for (int o = 16; o > 0; o >>= 1) acc += __shfl_xor_sync(0xffffffffu, acc, o);
    if (lane == 0) out[warp] = 1.0f / (1.0f + expf(-(acc + bl[0])));
}

// ------------------------------------------------------------------ launch
extern "C" void kernel_launch(void* const* d_in, const int* in_sizes, int n_in,
                              void* d_out, int out_size) {
    const void*  ei   = d_in[0];                 // [2, E] int32 or int64
    const float* X    = (const float*)d_in[1];   // [NN, 128]
    const void*  mask = d_in[2];                 // [P, 2] int32 or int64
    const float* W1   = (const float*)d_in[3];   // [128, 256]
    const float* b1   = (const float*)d_in[4];   // [256]
    const float* W2   = (const float*)d_in[5];   // [256, 128]
    const float* b2   = (const float*)d_in[6];   // [128]
    const float* Wl   = (const float*)d_in[7];   // [256, 1]
    const float* bl   = (const float*)d_in[8];   // [1]
    float* out = (float*)d_out;

    int E = in_sizes[0] / 2;
    int P = out_size;

    float *Y1, *H1, *Z, *H2;
    cudaGetSymbolAddress((void**)&Y1, g_Y1);
    cudaGetSymbolAddress((void**)&H1, g_H1);
    cudaGetSymbolAddress((void**)&Z,  g_Z);
    cudaGetSymbolAddress((void**)&H2, g_H2);

    const int T = 256;
    // index dtype detection + conversion to int32 scratch
    k_detect<<<1, 1>>>(ei);
    k_convert_edges<<<(E + T - 1) / T, T>>>(ei, E);
    k_convert_mask <<<(P + T - 1) / T, T>>>(mask, P);

    // degrees + dinv
    k_init_deg <<<(NN + T - 1) / T, T>>>();
    k_count_deg<<<(E  + T - 1) / T, T>>>(E);
    k_dinv     <<<(NN + T - 1) / T, T>>>();

    // layer 1: Y1 = S @ X ; H1 = relu(Y1 @ W1 + b1)
    int n4 = NN * (NF / 4);
    k_selfloop_init<<<(n4 + T - 1) / T, T>>>(X, Y1, nullptr);
    k_scatter<<<(int)(((size_t)E * 32 + T - 1) / T), T>>>(X, Y1, E);
    k_sgemm<<<dim3((NN + 127) / 128, NH / 128), 256>>>(Y1, W1, b1, H1,
                                                       NN, NH, NF, 1);

    // layer 2: Z = H1 @ W2 ; H2 = S @ Z + b2
    k_sgemm<<<dim3((NN + 127) / 128, NF / 128), 256>>>(H1, W2, nullptr, Z,
                                                       NN, NF, NH, 0);
    k_selfloop_init<<<(n4 + T - 1) / T, T>>>(Z, H2, b2);
    k_scatter<<<(int)(((size_t)E * 32 + T - 1) / T), T>>>(Z, H2, E);

    // link prediction
    k_pairs<<<(int)(((size_t)P * 32 + T - 1) / T), T>>>(Wl, bl, out, P);
}

// round 6
// speedup vs baseline: 2.5149x; 2.5149x over previous
#include <cuda_runtime.h>
#include <math.h>

#define NN 50000          // nodes
#define NF 128            // feature width (layer-1 in, layer-2 out)
#define NH 256            // hidden width
#define EMAX 800000
#define PMAX 100000
#define SCAN_B 1024
#define NBLK ((NN + SCAN_B - 1) / SCAN_B)   // 49

// ---- scratch (device globals; no allocation allowed) ----
__device__ int   g_is64;
__device__ int   g_row [EMAX];
__device__ int   g_col [EMAX];
__device__ int   g_eidx[EMAX];              // CSR: src node per (dst-sorted) slot
__device__ int   g_cnt [NN];                // in-degree (no self loop)
__device__ int   g_cur [NN];                // fill cursors
__device__ int   g_rowptr[NN + 1];
__device__ int   g_bsum[NBLK];
__device__ int   g_ma  [PMAX];
__device__ int   g_mb  [PMAX];
__device__ float g_dinv[NN];
__device__ float g_Y1  [(size_t)NN * NF];   // S @ X
__device__ float g_H1  [(size_t)NN * NH];   // relu(Y1 @ W1 + b1)
__device__ float g_Z   [(size_t)NN * NF];   // H1 @ W2
__device__ float g_H2  [(size_t)NN * NF];   // S @ Z + b2

// ---------------------------------------------------- index dtype detect
// int64 node ids are all in [0, NN); int32 data viewed as int64 fuses random
// pairs into huge values. Sample 8 entries; all-valid => int64.
__global__ void k_detect(const void* __restrict__ ei) {
    const long long* p = (const long long*)ei;
    int ok = 1;
    for (int i = 0; i < 8; i++) {
        long long v = p[i];
        if (v < 0 || v >= NN) ok = 0;
    }
    g_is64 = ok;
}

__global__ void k_zero_cnt() {
    int i = blockIdx.x * blockDim.x + threadIdx.x;
    if (i < NN) { g_cnt[i] = 0; g_cur[i] = 0; }
}

// convert indices to int32 scratch + count in-degrees
__global__ void k_convert_edges(const void* __restrict__ ei, int E) {
    int e = blockIdx.x * blockDim.x + threadIdx.x;
    if (e >= E) return;
    int r, c;
    if (g_is64) {
        const long long* p = (const long long*)ei;
        r = (int)p[e];
        c = (int)p[(size_t)E + e];
    } else {
        const int* p = (const int*)ei;
        r = p[e];
        c = p[E + e];
    }
    g_row[e] = r;
    g_col[e] = c;
    atomicAdd(&g_cnt[c], 1);
}

__global__ void k_convert_mask(const void* __restrict__ mask, int P) {
    int i = blockIdx.x * blockDim.x + threadIdx.x;
    if (i >= P) return;
    int a, b;
    if (g_is64) {
        const long long* p = (const long long*)mask;
        a = (int)p[(size_t)i * 2 + 0];
        b = (int)p[(size_t)i * 2 + 1];
    } else {
        const int* p = (const int*)mask;
        a = p[i * 2 + 0];
        b = p[i * 2 + 1];
    }
    g_ma[i] = a;
    g_mb[i] = b;
}

__global__ void k_dinv() {
    int i = blockIdx.x * blockDim.x + threadIdx.x;
    if (i < NN) g_dinv[i] = rsqrtf((float)g_cnt[i] + 1.0f);  // + self loop
}

// ------------------------------------------------- exclusive scan (3-phase)
__global__ __launch_bounds__(SCAN_B)
void k_scan_block() {
    __shared__ int sh[SCAN_B];
    int t = threadIdx.x;
    int idx = blockIdx.x * SCAN_B + t;
    int v = (idx < NN) ? g_cnt[idx] : 0;
    sh[t] = v;
    __syncthreads();
    // Hillis-Steele inclusive scan
    for (int off = 1; off < SCAN_B; off <<= 1) {
        int add = (t >= off) ? sh[t - off] : 0;
        __syncthreads();
        sh[t] += add;
        __syncthreads();
    }
    if (idx < NN) g_rowptr[idx] = sh[t] - v;      // exclusive within block
    if (t == SCAN_B - 1) g_bsum[blockIdx.x] = sh[t];
}

__global__ void k_scan_sums() {
    if (threadIdx.x == 0) {
        int acc = 0;
        for (int b = 0; b < NBLK; b++) {
            int s = g_bsum[b];
            g_bsum[b] = acc;
            acc += s;
        }
    }
}

__global__ void k_scan_add(int E) {
    int idx = blockIdx.x * blockDim.x + threadIdx.x;
    if (idx < NN) g_rowptr[idx] += g_bsum[idx >> 10];
    if (idx == 0) g_rowptr[NN] = E;
}

// ------------------------------------------------------------- CSR fill
__global__ void k_fill(int E) {
    int e = blockIdx.x * blockDim.x + threadIdx.x;
    if (e >= E) return;
    int c = g_col[e];
    int pos = g_rowptr[c] + atomicAdd(&g_cur[c], 1);
    g_eidx[pos] = g_row[e];
}

// ----------------------------------------------------------------- gather
// warp per node: dst[n] = dinv[n]^2*src[n] + sum_e dinv[r]*dinv[n]*src[r] (+bias)
__global__ __launch_bounds__(256)
void k_gather(const float* __restrict__ src, float* __restrict__ dst,
              const float* __restrict__ bias) {
    int node = (blockIdx.x * blockDim.x + threadIdx.x) >> 5;
    if (node >= NN) return;
    int lane = threadIdx.x & 31;
    float dc = g_dinv[node];

    // self-loop term
    float4 v = ((const float4*)(src + (size_t)node * NF))[lane];
    float ws = dc * dc;
    float4 acc;
    acc.x = ws * v.x; acc.y = ws * v.y; acc.z = ws * v.z; acc.w = ws * v.w;

    int beg = g_rowptr[node];
    int end = g_rowptr[node + 1];
#pragma unroll 4
    for (int j = beg; j < end; j++) {
        int r = __ldg(&g_eidx[j]);
        float w = __ldg(&g_dinv[r]) * dc;
        float4 u = ((const float4*)(src + (size_t)r * NF))[lane];
        acc.x += w * u.x; acc.y += w * u.y;
        acc.z += w * u.z; acc.w += w * u.w;
    }
    if (bias) {
        float4 b = ((const float4*)bias)[lane];
        acc.x += b.x; acc.y += b.y; acc.z += b.z; acc.w += b.w;
    }
    ((float4*)(dst + (size_t)node * NF))[lane] = acc;
}

// ------------------------------------------------------------------ SGEMM
// C[M,N] = A[M,K] @ B[K,N]  (+bias per col)  (optional relu)
__global__ __launch_bounds__(256)
void k_sgemm(const float* __restrict__ A, const float* __restrict__ B,
             const float* __restrict__ bias, float* __restrict__ C,
             int M, int N, int K, int relu) {
    const int BM = 128, BN = 128, BK = 16;
    __shared__ float As[BK * BM];   // transposed: As[k][m]
    __shared__ float Bs[BK * BN];   // Bs[k][n]

    int tid = threadIdx.x;
    int tx = tid & 15;
    int ty = tid >> 4;
    int rowBlock = blockIdx.x * BM;
    int colBlock = blockIdx.y * BN;

    float acc[8][8];
#pragma unroll
    for (int i = 0; i < 8; i++)
#pragma unroll
        for (int j = 0; j < 8; j++) acc[i][j] = 0.0f;

    for (int k0 = 0; k0 < K; k0 += BK) {
#pragma unroll
        for (int l = 0; l < 2; l++) {
            int fi = tid + l * 256;
            int ar = fi >> 2;
            int ak = (fi & 3) << 2;
            float4 v = make_float4(0.f, 0.f, 0.f, 0.f);
            int grow = rowBlock + ar;
            if (grow < M)
                v = *(const float4*)(A + (size_t)grow * K + k0 + ak);
            As[(ak + 0) * BM + ar] = v.x;
            As[(ak + 1) * BM + ar] = v.y;
            As[(ak + 2) * BM + ar] = v.z;
            As[(ak + 3) * BM + ar] = v.w;
            int bk = fi >> 5;
            int bn = (fi & 31) << 2;
            float4 w = *(const float4*)(B + (size_t)(k0 + bk) * N + colBlock + bn);
            *(float4*)&Bs[bk * BN + bn] = w;
        }
        __syncthreads();

#pragma unroll
        for (int kk = 0; kk < BK; kk++) {
            float a0[4], a1[4], b0[4], b1[4];
            *(float4*)a0 = *(const float4*)&As[kk * BM + ty * 4];
            *(float4*)a1 = *(const float4*)&As[kk * BM + 64 + ty * 4];
            *(float4*)b0 = *(const float4*)&Bs[kk * BN + tx * 4];
            *(float4*)b1 = *(const float4*)&Bs[kk * BN + 64 + tx * 4];
#pragma unroll
            for (int i = 0; i < 4; i++) {
#pragma unroll
                for (int j = 0; j < 4; j++) {
                    acc[i][j]         += a0[i] * b0[j];
                    acc[i][j + 4]     += a0[i] * b1[j];
                    acc[i + 4][j]     += a1[i] * b0[j];
                    acc[i + 4][j + 4] += a1[i] * b1[j];
                }
            }
        }
        __syncthreads();
    }

#pragma unroll
    for (int ih = 0; ih < 2; ih++) {
#pragma unroll
        for (int i = 0; i < 4; i++) {
            int row = rowBlock + ih * 64 + ty * 4 + i;
            if (row >= M) continue;
#pragma unroll
            for (int jh = 0; jh < 2; jh++) {
                int col = colBlock + jh * 64 + tx * 4;
                float* a = &acc[ih * 4 + i][jh * 4];
                float4 o = make_float4(a[0], a[1], a[2], a[3]);
                if (bias) {
                    float4 b = *(const float4*)(bias + col);
                    o.x += b.x; o.y += b.y; o.z += b.z; o.w += b.w;
                }
                if (relu) {
                    o.x = fmaxf(o.x, 0.f); o.y = fmaxf(o.y, 0.f);
                    o.z = fmaxf(o.z, 0.f); o.w = fmaxf(o.w, 0.f);
                }
                *(float4*)(C + (size_t)row * N + col) = o;
            }
        }
    }
}

// --------------------------------------------------------------- pair dot
__global__ void k_pairs(const float* __restrict__ Wl,
                        const float* __restrict__ bl,
                        float* __restrict__ out, int P) {
    int warp = (blockIdx.x * blockDim.x + threadIdx.x) >> 5;
    if (warp >= P) return;
    int lane = threadIdx.x & 31;
    int a = g_ma[warp];
    int b = g_mb[warp];
    float4 va = ((const float4*)(g_H2 + (size_t)a * NF))[lane];
    float4 wa = ((const float4*)Wl)[lane];
    float4 vb = ((const float4*)(g_H2 + (size_t)b * NF))[lane];
    float4 wb = ((const float4*)(Wl + NF))[lane];
    float acc = va.x * wa.x + va.y * wa.y + va.z * wa.z + va.w * wa.w
              + vb.x * wb.x + vb.y * wb.y + vb.z * wb.z + vb.w * wb.w;
#pragma unroll
    for (int o = 16; o > 0; o >>= 1) acc += __shfl_xor_sync(0xffffffffu, acc, o);
    if (lane == 0) out[warp] = 1.0f / (1.0f + expf(-(acc + bl[0])));
}

// ------------------------------------------------------------------ launch
extern "C" void kernel_launch(void* const* d_in, const int* in_sizes, int n_in,
                              void* d_out, int out_size) {
    const void*  ei   = d_in[0];                 // [2, E] int32 or int64
    const float* X    = (const float*)d_in[1];   // [NN, 128]
    const void*  mask = d_in[2];                 // [P, 2] int32 or int64
    const float* W1   = (const float*)d_in[3];   // [128, 256]
    const float* b1   = (const float*)d_in[4];   // [256]
    const float* W2   = (const float*)d_in[5];   // [256, 128]
    const float* b2   = (const float*)d_in[6];   // [128]
    const float* Wl   = (const float*)d_in[7];   // [256, 1]
    const float* bl   = (const float*)d_in[8];   // [1]
    float* out = (float*)d_out;

    int E = in_sizes[0] / 2;
    int P = out_size;

    float *Y1, *H1, *Z, *H2;
    cudaGetSymbolAddress((void**)&Y1, g_Y1);
    cudaGetSymbolAddress((void**)&H1, g_H1);
    cudaGetSymbolAddress((void**)&Z,  g_Z);
    cudaGetSymbolAddress((void**)&H2, g_H2);

    const int T = 256;
    // prologue: dtype detect, int32 conversion, degree count, CSR build
    k_detect<<<1, 1>>>(ei);
    k_zero_cnt<<<(NN + T - 1) / T, T>>>();
    k_convert_edges<<<(E + T - 1) / T, T>>>(ei, E);
    k_convert_mask <<<(P + T - 1) / T, T>>>(mask, P);
    k_dinv<<<(NN + T - 1) / T, T>>>();
    k_scan_block<<<NBLK, SCAN_B>>>();
    k_scan_sums<<<1, 32>>>();
    k_scan_add<<<(NN + T - 1) / T, T>>>(E);
    k_fill<<<(E + T - 1) / T, T>>>(E);

    // layer 1: Y1 = S @ X ; H1 = relu(Y1 @ W1 + b1)
    k_gather<<<(NN * 32 + T - 1) / T, T>>>(X, Y1, nullptr);
    k_sgemm<<<dim3((NN + 127) / 128, NH / 128), 256>>>(Y1, W1, b1, H1,
                                                       NN, NH, NF, 1);

    // layer 2: Z = H1 @ W2 ; H2 = S @ Z + b2
    k_sgemm<<<dim3((NN + 127) / 128, NF / 128), 256>>>(H1, W2, nullptr, Z,
                                                       NN, NF, NH, 0);
    k_gather<<<(NN * 32 + T - 1) / T, T>>>(Z, H2, b2);

    // link prediction
    k_pairs<<<(int)(((size_t)P * 32 + T - 1) / T), T>>>(Wl, bl, out, P);
}